// round 17
// baseline (speedup 1.0000x reference)
#include <cuda_runtime.h>
#include <cuda_fp16.h>
#include <cstddef>
#include <cstdint>
#include <math.h>

// ---------------------------------------------------------------------------
// Problem constants
// ---------------------------------------------------------------------------
#define BATCH 8
#define CH    512
#define KDIM  128
#define EPSV  1e-5f

#define HW1 9216           // 96*96
#define HW2 2304           // 48*48
#define HW3 576            // 24*24
#define HW4 144            // 12*12
#define KC  4608           // 512*9 im2col K

// ---------------------------------------------------------------------------
// Scratch (allocation-free: __device__ globals)
// ---------------------------------------------------------------------------
__device__ float g_scale[CH];
__device__ float g_shift[CH];

__device__ __half g_c2[BATCH * CH * HW2];            // conv out fp16 [c][pix]
__device__ __half g_c3[BATCH * CH * HW3];
__device__ __half g_c4[BATCH * CH * HW4];
__device__ __half g_eh[(size_t)BATCH * HW2 * HW2];   // fp16 energy
__device__ __half g_ph[(size_t)BATCH * HW2 * HW2];   // fp16 softmax probs

__device__ __half g_p2h[BATCH * CH * HW2];
__device__ __half g_p3h[BATCH * CH * HW3];
__device__ __half g_p4h[BATCH * CH * HW4];
__device__ __half g_t3h[BATCH * CH * HW3];
__device__ __half g_t2h[BATCH * CH * HW2];

__device__ __half g_xh [(size_t)BATCH * HW1 * CH];   // x transposed fp16 [pix][c]
__device__ __half g_d2h[(size_t)BATCH * HW2 * CH];   // bn+relu+T fp16
__device__ __half g_d3h[(size_t)BATCH * HW3 * CH];
__device__ __half g_d4h[(size_t)BATCH * HW4 * CH];
__device__ __half g_qkt[(size_t)BATCH * HW2 * 2 * KDIM]; // q|k fp16 [pix][256]
__device__ __half g_vh [(size_t)BATCH * CH * HW2];   // v fp16 [c][pix]

// per-level converted weights
__device__ __half g_wh2[CH * KC];
__device__ __half g_wh3[CH * KC];
__device__ __half g_wh4[CH * KC];
__device__ __half g_qkwh2[2 * KDIM * CH];
__device__ __half g_qkwh3[2 * KDIM * CH];
__device__ __half g_qkwh4[2 * KDIM * CH];
__device__ __half g_vwh2[CH * CH];
__device__ __half g_vwh3[CH * CH];
__device__ __half g_vwh4[CH * CH];
__device__ float  g_qkb2[2 * KDIM];
__device__ float  g_qkb3[2 * KDIM];
__device__ float  g_qkb4[2 * KDIM];

// ---------------------------------------------------------------------------
// Load/store helpers
// ---------------------------------------------------------------------------
__device__ __forceinline__ float ldv(const float* p)  { return *p; }
__device__ __forceinline__ float ldv(const __half* p) { return __half2float(*p); }
__device__ __forceinline__ void stv(float* p, float v)  { *p = v; }
__device__ __forceinline__ void stv(__half* p, float v) { *p = __float2half(v); }

// ---------------------------------------------------------------------------
// FMA-pipe fast exp: e^x for x <= 0 (softmax domain). No MUFU.
// 2^t split by magic-number rounding; deg-4 poly for 2^f, f in [-0.5, 0.5].
// rel err <= ~4e-5.
// ---------------------------------------------------------------------------
__device__ __forceinline__ float fexpf(float x)
{
    x = fmaxf(x, -80.f);                                   // avoid underflow
    float t = __fmaf_rn(x, 1.44269504f, 12582912.f);       // x*log2e + 1.5*2^23
    int   e = __float_as_int(t) - 0x4B400000;              // round-to-nearest int
    float f = __fmaf_rn(x, 1.44269504f, -(t - 12582912.f));// frac in [-0.5, 0.5]
    float p = 0.0096181291f;
    p = __fmaf_rn(p, f, 0.055504109f);
    p = __fmaf_rn(p, f, 0.24022651f);
    p = __fmaf_rn(p, f, 0.69314718f);
    p = __fmaf_rn(p, f, 1.0f);
    return __int_as_float(__float_as_int(p) + (e << 23));  // p * 2^e
}

// ---------------------------------------------------------------------------
// One-shot weight prep: converts everything for all 3 levels.
// ---------------------------------------------------------------------------
#define CONVN (CH * KC)            // 2359296
#define QKWN  (2 * KDIM * CH)      // 131072
#define VWN   (CH * CH)            // 262144
#define PREP_TOTAL (3 * CONVN + 3 * QKWN + 3 * VWN + 3 * 256)

__global__ void prep_w_k(const float* __restrict__ w2, const float* __restrict__ w3,
                         const float* __restrict__ w4,
                         const float* __restrict__ qw2, const float* __restrict__ kw2,
                         const float* __restrict__ vw2,
                         const float* __restrict__ qb2, const float* __restrict__ kb2,
                         const float* __restrict__ qw3, const float* __restrict__ kw3,
                         const float* __restrict__ vw3,
                         const float* __restrict__ qb3, const float* __restrict__ kb3,
                         const float* __restrict__ qw4, const float* __restrict__ kw4,
                         const float* __restrict__ vw4,
                         const float* __restrict__ qb4, const float* __restrict__ kb4)
{
    int i = blockIdx.x * blockDim.x + threadIdx.x;
    if (i >= PREP_TOTAL) return;

    if (i < 3 * CONVN) {
        int lvl = i / CONVN, j = i - lvl * CONVN;
        const float* w = lvl == 0 ? w2 : (lvl == 1 ? w3 : w4);
        __half* o = lvl == 0 ? g_wh2 : (lvl == 1 ? g_wh3 : g_wh4);
        int ic = j & 511, kk = (j >> 9) % 9, oc = j / KC;
        o[j] = __float2half(w[((size_t)oc * CH + ic) * 9 + kk]);
        return;
    }
    i -= 3 * CONVN;
    if (i < 3 * QKWN) {
        int lvl = i / QKWN, j = i - lvl * QKWN;
        const float* q = lvl == 0 ? qw2 : (lvl == 1 ? qw3 : qw4);
        const float* k = lvl == 0 ? kw2 : (lvl == 1 ? kw3 : kw4);
        __half* o = lvl == 0 ? g_qkwh2 : (lvl == 1 ? g_qkwh3 : g_qkwh4);
        o[j] = __float2half(j < KDIM * CH ? q[j] : k[j - KDIM * CH]);
        return;
    }
    i -= 3 * QKWN;
    if (i < 3 * VWN) {
        int lvl = i / VWN, j = i - lvl * VWN;
        const float* v = lvl == 0 ? vw2 : (lvl == 1 ? vw3 : vw4);
        __half* o = lvl == 0 ? g_vwh2 : (lvl == 1 ? g_vwh3 : g_vwh4);
        o[j] = __float2half(v[j]);
        return;
    }
    i -= 3 * VWN;
    {
        int lvl = i / 256, j = i - lvl * 256;
        const float* q = lvl == 0 ? qb2 : (lvl == 1 ? qb3 : qb4);
        const float* k = lvl == 0 ? kb2 : (lvl == 1 ? kb3 : kb4);
        float* o = lvl == 0 ? g_qkb2 : (lvl == 1 ? g_qkb3 : g_qkb4);
        o[j] = j < KDIM ? q[j] : k[j - KDIM];
    }
}

// ---------------------------------------------------------------------------
// Transpose (+optional BN+ReLU): [b][c][pix] (TS) -> fp16 [b][pix][c]
// ---------------------------------------------------------------------------
template <int BN_ON, typename TS>
__global__ void bnT_k(const TS* __restrict__ y,
                      const float* __restrict__ scale,
                      const float* __restrict__ shift,
                      __half* __restrict__ out, int HW)
{
    __shared__ float tile[32][33];
    int b = blockIdx.z;
    int p0 = blockIdx.x * 32, c0 = blockIdx.y * 32;
    int tx = threadIdx.x, ty = threadIdx.y;
#pragma unroll
    for (int j = 0; j < 4; j++) {
        int c = c0 + ty + j * 8;
        int p = p0 + tx;
        float v = 0.f;
        if (p < HW) v = ldv(y + ((size_t)b * CH + c) * HW + p);
        if (BN_ON) { v = v * scale[c] + shift[c]; v = v > 0.f ? v : 0.f; }
        tile[ty + j * 8][tx] = v;
    }
    __syncthreads();
#pragma unroll
    for (int j = 0; j < 4; j++) {
        int p = p0 + ty + j * 8;
        int c = c0 + tx;
        if (p < HW) out[((size_t)b * HW + p) * CH + c] = __float2half(tile[tx][ty + j * 8]);
    }
}

// ---------------------------------------------------------------------------
// fp16 tensor-core GEMM, cp.async 3-stage pipeline, K-chunk 64, ldmatrix.
// C(M,N) = A(M,K)[m][k] * B(N,K)[n][k]^T, k-contiguous fp16 operands.
// CDIM > 0: implicit-im2col B operand (3x3 s2 p1 conv, input [pix][c],
// spatial CDIM x CDIM).  OUT=0: fp32 C; OUT=1: fp16 C.
// Epilogue: C = s*acc + biasM[row] + biasN[col] + addm (all optional).
// ---------------------------------------------------------------------------
#define GH_STG (128 * 72)                 // halves per operand per stage
#define GH_SMEM (6 * GH_STG * 2)          // 110592 bytes (3 stages x 2 ops)

template <int OUT, int CDIM>
__global__ __launch_bounds__(256)
void gemm_h(const __half* __restrict__ A, const __half* __restrict__ B,
            float* __restrict__ Cf, __half* __restrict__ Ch,
            int M, int N, int K, int lda, int ldb,
            long long sA, long long sB, long long sC,
            const float* __restrict__ biasM, const float* __restrict__ biasN,
            const __half* __restrict__ addm, const float* __restrict__ scl)
{
    extern __shared__ __align__(16) __half smh[];

    const int bz = blockIdx.z;
    const __half* Ab = A + (size_t)bz * sA;
    const __half* Bb = B + (size_t)bz * sB;

    const int n0 = blockIdx.x * 128, m0 = blockIdx.y * 128;
    const int t = threadIdx.x, lane = t & 31, w = t >> 5;
    const int wm = w & 1, wn = w >> 1;
    const int g = lane >> 2, tg = lane & 3;

    const uint32_t sb0 = (uint32_t)__cvta_generic_to_shared(smh);

    const int aRow = (lane & 7) + ((lane >> 3) & 1) * 8;
    const int aK   = ((lane >> 4) & 1) * 8;
    const int bRow = (lane & 7) + ((lane >> 4) & 1) * 8;
    const int bK   = ((lane >> 3) & 1) * 8;

    auto loadA = [&](uint32_t sb, int k0) {
#pragma unroll
        for (int i = 0; i < 4; i++) {
            int u = t + i * 256;
            int row = u >> 3, ch = (u & 7) << 3;
            bool p = (m0 + row < M) && (k0 + ch < K);
            const __half* sp = p ? Ab + (size_t)(m0 + row) * lda + k0 + ch : Ab;
            asm volatile("cp.async.cg.shared.global [%0], [%1], 16, %2;"
                         :: "r"(sb + (uint32_t)(row * 72 + ch) * 2u),
                            "l"(sp), "r"(p ? 16 : 0));
        }
    };
    auto loadB = [&](uint32_t sb, int k0) {
#pragma unroll
        for (int i = 0; i < 4; i++) {
            int u = t + i * 256;
            int row = u >> 3, ch = (u & 7) << 3;
            if (CDIM == 0) {
                bool p = (n0 + row < N) && (k0 + ch < K);
                const __half* sp = p ? Bb + (size_t)(n0 + row) * ldb + k0 + ch : Bb;
                asm volatile("cp.async.cg.shared.global [%0], [%1], 16, %2;"
                             :: "r"(sb + (uint32_t)(row * 72 + ch) * 2u),
                                "l"(sp), "r"(p ? 16 : 0));
            } else {
                constexpr int OW = CDIM / 2;
                int k   = k0 + ch;
                int kk  = k >> 9;
                int icc = k & 511;
                int pix = n0 + row;
                int oh = pix / OW, ow = pix - oh * OW;
                int kh = kk / 3, kw = kk - kh * 3;
                int ih = 2 * oh - 1 + kh, iw = 2 * ow - 1 + kw;
                bool p = (pix < N) && (ih >= 0) && (ih < CDIM)
                       && (iw >= 0) && (iw < CDIM);
                const __half* sp = p ? Bb + ((size_t)ih * CDIM + iw) * CH + icc : Bb;
                asm volatile("cp.async.cg.shared.global [%0], [%1], 16, %2;"
                             :: "r"(sb + (uint32_t)(row * 72 + ch) * 2u),
                                "l"(sp), "r"(p ? 16 : 0));
            }
        }
    };

    float acc[4][4][4];
#pragma unroll
    for (int a = 0; a < 4; a++)
#pragma unroll
        for (int b = 0; b < 4; b++)
#pragma unroll
            for (int c = 0; c < 4; c++) acc[a][b][c] = 0.f;

    const uint32_t stA[3] = { sb0, sb0 + GH_STG * 2, sb0 + 2 * GH_STG * 2 };
    const uint32_t stB[3] = { sb0 + 3 * GH_STG * 2, sb0 + 4 * GH_STG * 2,
                              sb0 + 5 * GH_STG * 2 };

    const int nk = (K + 63) >> 6;
    loadA(stA[0], 0);
    loadB(stB[0], 0);
    asm volatile("cp.async.commit_group;");
    if (nk > 1) {
        loadA(stA[1], 64);
        loadB(stB[1], 64);
    }
    asm volatile("cp.async.commit_group;");

    int cur = 0, nxt = 2;
    for (int kt = 0; kt < nk; kt++) {
        asm volatile("cp.async.wait_group 1;");
        __syncthreads();

        if (kt + 2 < nk) {
            loadA(stA[nxt], (kt + 2) * 64);
            loadB(stB[nxt], (kt + 2) * 64);
        }
        asm volatile("cp.async.commit_group;");

        const uint32_t As = stA[cur];
        const uint32_t Bs = stB[cur];

#pragma unroll
        for (int s = 0; s < 64; s += 16) {
            uint32_t a[4][4], b[4][2];
#pragma unroll
            for (int mt = 0; mt < 4; mt++) {
                uint32_t ad = As + (uint32_t)((wm * 64 + mt * 16 + aRow) * 72
                                              + s + aK) * 2u;
                asm volatile(
                    "ldmatrix.sync.aligned.m8n8.x4.shared.b16 {%0,%1,%2,%3}, [%4];"
                    : "=r"(a[mt][0]), "=r"(a[mt][1]), "=r"(a[mt][2]), "=r"(a[mt][3])
                    : "r"(ad));
            }
#pragma unroll
            for (int nt2 = 0; nt2 < 2; nt2++) {
                uint32_t bd = Bs + (uint32_t)((wn * 32 + nt2 * 16 + bRow) * 72
                                              + s + bK) * 2u;
                asm volatile(
                    "ldmatrix.sync.aligned.m8n8.x4.shared.b16 {%0,%1,%2,%3}, [%4];"
                    : "=r"(b[2 * nt2][0]), "=r"(b[2 * nt2][1]),
                      "=r"(b[2 * nt2 + 1][0]), "=r"(b[2 * nt2 + 1][1])
                    : "r"(bd));
            }
#pragma unroll
            for (int mt = 0; mt < 4; mt++)
#pragma unroll
                for (int nt = 0; nt < 4; nt++) {
                    asm volatile(
                        "mma.sync.aligned.m16n8k16.row.col.f32.f16.f16.f32 "
                        "{%0,%1,%2,%3}, {%4,%5,%6,%7}, {%8,%9}, {%0,%1,%2,%3};"
                        : "+f"(acc[mt][nt][0]), "+f"(acc[mt][nt][1]),
                          "+f"(acc[mt][nt][2]), "+f"(acc[mt][nt][3])
                        : "r"(a[mt][0]), "r"(a[mt][1]), "r"(a[mt][2]), "r"(a[mt][3]),
                          "r"(b[nt][0]), "r"(b[nt][1]));
                }
        }
        cur = (cur + 1) == 3 ? 0 : cur + 1;
        nxt = (nxt + 1) == 3 ? 0 : nxt + 1;
    }

    float s = scl ? *scl : 1.f;
#pragma unroll
    for (int mt = 0; mt < 4; mt++) {
#pragma unroll
        for (int half = 0; half < 2; half++) {
            int gr = m0 + wm * 64 + mt * 16 + g + half * 8;
            if (gr >= M) continue;
            float bm = biasM ? biasM[gr] : 0.f;
#pragma unroll
            for (int nt = 0; nt < 4; nt++) {
                int gc = n0 + wn * 32 + nt * 8 + tg * 2;
                if (gc + 1 >= N) continue;
                float v0 = s * acc[mt][nt][half * 2 + 0] + bm;
                float v1 = s * acc[mt][nt][half * 2 + 1] + bm;
                if (biasN) { v0 += biasN[gc]; v1 += biasN[gc + 1]; }
                size_t idx = (size_t)bz * sC + (size_t)gr * N + gc;
                if (addm) {
                    __half2 av = *(const __half2*)(addm + idx);
                    v0 += __half2float(av.x);
                    v1 += __half2float(av.y);
                }
                if (OUT == 0) {
                    *(float2*)(Cf + idx) = make_float2(v0, v1);
                } else {
                    *(__half2*)(Ch + idx) = __floats2half2_rn(v0, v1);
                }
            }
        }
    }
}

// ---------------------------------------------------------------------------
// BN statistics from fp16 conv output (fp32 accumulators).
// ---------------------------------------------------------------------------
__global__ void bn_stats_k(const __half* __restrict__ y, int HW,
                           const float* __restrict__ gw,
                           const float* __restrict__ gb,
                           float* __restrict__ scale,
                           float* __restrict__ shift)
{
    const int c = blockIdx.x;
    const int t = threadIdx.x;
    float s = 0.f, s2 = 0.f;
    for (int b = 0; b < BATCH; b++) {
        const __half* p = y + ((size_t)b * CH + c) * HW;
        for (int i = t; i < HW; i += 256) {
            float v = __half2float(p[i]);
            s += v; s2 += v * v;
        }
    }
#pragma unroll
    for (int o = 16; o; o >>= 1) {
        s  += __shfl_xor_sync(0xffffffffu, s, o);
        s2 += __shfl_xor_sync(0xffffffffu, s2, o);
    }
    __shared__ float r1[8], r2[8];
    if ((t & 31) == 0) { r1[t >> 5] = s; r2[t >> 5] = s2; }
    __syncthreads();
    if (t == 0) {
        float a = 0.f, b2 = 0.f;
        for (int i = 0; i < 8; i++) { a += r1[i]; b2 += r2[i]; }
        float n   = (float)(BATCH * HW);
        float m   = a / n;
        float var = b2 / n - m * m;
        float sc  = gw[c] * rsqrtf(var + EPSV);
        scale[c] = sc;
        shift[c] = gb[c] - m * sc;
    }
}

// ---------------------------------------------------------------------------
// Row softmax: fp16 energy in, fp16 probs out. FMA-pipe fast exp (no MUFU).
// ---------------------------------------------------------------------------
__global__ void softmax_k(const __half* __restrict__ E, __half* __restrict__ P, int L)
{
    extern __shared__ float sm[];
    float* red = sm + L;
    const size_t row = blockIdx.x;
    const __half* p = E + row * (size_t)L;
    __half* q = P + row * (size_t)L;
    const int t = threadIdx.x;

    float mx = -3.4e38f;
    for (int i = t; i < L; i += 256) {
        float v = __half2float(p[i]);
        sm[i] = v;
        mx = fmaxf(mx, v);
    }
#pragma unroll
    for (int o = 16; o; o >>= 1) mx = fmaxf(mx, __shfl_xor_sync(0xffffffffu, mx, o));
    if ((t & 31) == 0) red[t >> 5] = mx;
    __syncthreads();
    if (t < 32) {
        float v = (t < 8) ? red[t] : -3.4e38f;
#pragma unroll
        for (int o = 4; o; o >>= 1) v = fmaxf(v, __shfl_xor_sync(0xffffffffu, v, o));
        if (t == 0) red[0] = v;
    }
    __syncthreads();
    mx = red[0];
    __syncthreads();

    float ss = 0.f;
    for (int i = t; i < L; i += 256) {
        float e = fexpf(sm[i] - mx);
        sm[i] = e;
        ss += e;
    }
#pragma unroll
    for (int o = 16; o; o >>= 1) ss += __shfl_xor_sync(0xffffffffu, ss, o);
    if ((t & 31) == 0) red[t >> 5] = ss;
    __syncthreads();
    if (t < 32) {
        float v = (t < 8) ? red[t] : 0.f;
#pragma unroll
        for (int o = 4; o; o >>= 1) v += __shfl_xor_sync(0xffffffffu, v, o);
        if (t == 0) red[0] = v;
    }
    __syncthreads();
    float inv = 1.f / red[0];
    for (int i = t; i < L; i += 256) q[i] = __float2half(sm[i] * inv);
}

// ---------------------------------------------------------------------------
// dst = add + g * bilinear_upsample(src)   (templated element types)
// ---------------------------------------------------------------------------
template <typename TS, typename TA, typename TD>
__global__ void up_fma_k(const TS* __restrict__ src, int SH, int SWd,
                         const TA* __restrict__ add, TD* __restrict__ dst,
                         int DH, int DW, const float* __restrict__ gptr,
                         size_t total)
{
    size_t i = (size_t)blockIdx.x * blockDim.x + threadIdx.x;
    if (i >= total) return;
    int ox = (int)(i % DW);
    int oy = (int)((i / DW) % DH);
    size_t bc = i / ((size_t)DW * DH);

    float ry = (float)(SH - 1) / (float)(DH - 1);
    float rx = (float)(SWd - 1) / (float)(DW - 1);
    float ys = oy * ry, xs = ox * rx;
    int y0 = (int)ys; if (y0 > SH - 1) y0 = SH - 1;
    int x0 = (int)xs; if (x0 > SWd - 1) x0 = SWd - 1;
    int y1 = min(y0 + 1, SH - 1);
    int x1 = min(x0 + 1, SWd - 1);
    float tty = ys - (float)y0, ttx = xs - (float)x0;

    const TS* sp = src + bc * (size_t)(SH * SWd);
    float v00 = ldv(sp + y0 * SWd + x0), v01 = ldv(sp + y0 * SWd + x1);
    float v10 = ldv(sp + y1 * SWd + x0), v11 = ldv(sp + y1 * SWd + x1);
    float val = v00 * (1.f - tty) * (1.f - ttx) + v01 * (1.f - tty) * ttx
              + v10 * tty * (1.f - ttx) + v11 * tty * ttx;
    float g = gptr ? *gptr : 1.f;
    stv(dst + i, ldv(add + i) + g * val);
}

// ---------------------------------------------------------------------------
// Host side
// ---------------------------------------------------------------------------
static inline unsigned cdiv(unsigned a, unsigned b) { return (a + b - 1) / b; }

struct Bufs {
    float *scale, *shift;
    __half *c2, *c3, *c4, *eh, *ph;
    __half *p2h, *p3h, *p4h, *t3h, *t2h;
    __half *xh, *d2h, *d3h, *d4h, *qkt, *vh;
    __half *wh2, *wh3, *wh4, *qkwh2, *qkwh3, *qkwh4, *vwh2, *vwh3, *vwh4;
    float *qkb2, *qkb3, *qkb4;
};

static void run_pam(const __half* dh, int HW,
                    const __half* qkwh, const float* qkb,
                    const __half* vwh, const float* vb,
                    const float* g, __half* pout, const Bufs& B)
{
    dim3 thr(256);
    unsigned nb = cdiv(HW, 128);
    long long dhS  = (long long)HW * CH;
    long long qkS  = (long long)HW * 2 * KDIM;
    long long vS   = (long long)CH * HW;
    long long aS   = (long long)HW * HW;

    // [q|k]^T = dh * qkw^T + qkb  (M=HW, N=256, K=512), fp16 out
    gemm_h<1, 0><<<dim3(2, nb, BATCH), thr, GH_SMEM>>>(dh, qkwh, nullptr, B.qkt,
        HW, 2 * KDIM, CH, CH, CH, dhS, 0, qkS, nullptr, qkb, nullptr, nullptr);
    // v = vw * d + vb  (M=512, N=HW, K=512), fp16 out
    gemm_h<1, 0><<<dim3(nb, 4, BATCH), thr, GH_SMEM>>>(vwh, dh, nullptr, B.vh,
        CH, HW, CH, CH, CH, 0, dhS, vS, vb, nullptr, nullptr, nullptr);
    // energy = q^T k  (M=N=HW, K=128), fp16 out
    gemm_h<1, 0><<<dim3(nb, nb, BATCH), thr, GH_SMEM>>>(B.qkt, B.qkt + KDIM,
        nullptr, B.eh, HW, HW, KDIM, 2 * KDIM, 2 * KDIM, qkS, qkS, aS,
        nullptr, nullptr, nullptr, nullptr);
    softmax_k<<<BATCH * HW, 256, (HW + 32) * sizeof(float)>>>(B.eh, B.ph, HW);
    // p = g*(v @ attn^T) + v  (M=512, N=HW, K=HW), fp16 out
    gemm_h<1, 0><<<dim3(nb, 4, BATCH), thr, GH_SMEM>>>(B.vh, B.ph, nullptr, pout,
        CH, HW, HW, HW, HW, vS, aS, vS, nullptr, nullptr, B.vh, g);
}

template <int IH>
static void run_conv(const __half* src_h, const __half* wh, __half* out)
{
    constexpr int OH = IH / 2, OHOW = OH * OH;
    gemm_h<1, IH><<<dim3(cdiv(OHOW, 128), 4, BATCH), dim3(256), GH_SMEM>>>(
        wh, src_h, nullptr, out, CH, OHOW, KC, KC, 0,
        0, (long long)IH * IH * CH, (long long)CH * OHOW,
        nullptr, nullptr, nullptr, nullptr);
}

extern "C" void kernel_launch(void* const* d_in, const int* in_sizes, int n_in,
                              void* d_out, int out_size)
{
    (void)in_sizes; (void)n_in; (void)out_size;

    cudaFuncSetAttribute(gemm_h<1, 0>,  cudaFuncAttributeMaxDynamicSharedMemorySize, GH_SMEM);
    cudaFuncSetAttribute(gemm_h<1, 96>, cudaFuncAttributeMaxDynamicSharedMemorySize, GH_SMEM);
    cudaFuncSetAttribute(gemm_h<1, 48>, cudaFuncAttributeMaxDynamicSharedMemorySize, GH_SMEM);
    cudaFuncSetAttribute(gemm_h<1, 24>, cudaFuncAttributeMaxDynamicSharedMemorySize, GH_SMEM);

    const float* x = (const float*)d_in[0];
    const float* w2   = (const float*)d_in[1];
    const float* bnw2 = (const float*)d_in[2];
    const float* bnb2 = (const float*)d_in[3];
    const float* w3   = (const float*)d_in[11];
    const float* bnw3 = (const float*)d_in[12];
    const float* bnb3 = (const float*)d_in[13];
    const float* w4   = (const float*)d_in[21];
    const float* bnw4 = (const float*)d_in[22];
    const float* bnb4 = (const float*)d_in[23];
    const float* gamma = (const float*)d_in[31];
    float* out = (float*)d_out;

    Bufs B;
    void* p;
    cudaGetSymbolAddress(&p, g_scale); B.scale = (float*)p;
    cudaGetSymbolAddress(&p, g_shift); B.shift = (float*)p;
    cudaGetSymbolAddress(&p, g_c2);    B.c2    = (__half*)p;
    cudaGetSymbolAddress(&p, g_c3);    B.c3    = (__half*)p;
    cudaGetSymbolAddress(&p, g_c4);    B.c4    = (__half*)p;
    cudaGetSymbolAddress(&p, g_eh);    B.eh    = (__half*)p;
    cudaGetSymbolAddress(&p, g_ph);    B.ph    = (__half*)p;
    cudaGetSymbolAddress(&p, g_p2h);   B.p2h   = (__half*)p;
    cudaGetSymbolAddress(&p, g_p3h);   B.p3h   = (__half*)p;
    cudaGetSymbolAddress(&p, g_p4h);   B.p4h   = (__half*)p;
    cudaGetSymbolAddress(&p, g_t3h);   B.t3h   = (__half*)p;
    cudaGetSymbolAddress(&p, g_t2h);   B.t2h   = (__half*)p;
    cudaGetSymbolAddress(&p, g_xh);    B.xh    = (__half*)p;
    cudaGetSymbolAddress(&p, g_d2h);   B.d2h   = (__half*)p;
    cudaGetSymbolAddress(&p, g_d3h);   B.d3h   = (__half*)p;
    cudaGetSymbolAddress(&p, g_d4h);   B.d4h   = (__half*)p;
    cudaGetSymbolAddress(&p, g_qkt);   B.qkt   = (__half*)p;
    cudaGetSymbolAddress(&p, g_vh);    B.vh    = (__half*)p;
    cudaGetSymbolAddress(&p, g_wh2);   B.wh2   = (__half*)p;
    cudaGetSymbolAddress(&p, g_wh3);   B.wh3   = (__half*)p;
    cudaGetSymbolAddress(&p, g_wh4);   B.wh4   = (__half*)p;
    cudaGetSymbolAddress(&p, g_qkwh2); B.qkwh2 = (__half*)p;
    cudaGetSymbolAddress(&p, g_qkwh3); B.qkwh3 = (__half*)p;
    cudaGetSymbolAddress(&p, g_qkwh4); B.qkwh4 = (__half*)p;
    cudaGetSymbolAddress(&p, g_vwh2);  B.vwh2  = (__half*)p;
    cudaGetSymbolAddress(&p, g_vwh3);  B.vwh3  = (__half*)p;
    cudaGetSymbolAddress(&p, g_vwh4);  B.vwh4  = (__half*)p;
    cudaGetSymbolAddress(&p, g_qkb2);  B.qkb2  = (float*)p;
    cudaGetSymbolAddress(&p, g_qkb3);  B.qkb3  = (float*)p;
    cudaGetSymbolAddress(&p, g_qkb4);  B.qkb4  = (float*)p;

    dim3 tb(32, 8);

    // one-shot weight prep for all levels
    prep_w_k<<<cdiv(PREP_TOTAL, 256), 256>>>(
        w2, w3, w4,
        (const float*)d_in[4],  (const float*)d_in[6],  (const float*)d_in[8],
        (const float*)d_in[5],  (const float*)d_in[7],
        (const float*)d_in[14], (const float*)d_in[16], (const float*)d_in[18],
        (const float*)d_in[15], (const float*)d_in[17],
        (const float*)d_in[24], (const float*)d_in[26], (const float*)d_in[28],
        (const float*)d_in[25], (const float*)d_in[27]);

    // x -> fp16 transposed [pix][c]
    bnT_k<0><<<dim3(cdiv(HW1, 32), 16, BATCH), tb>>>(x, (const float*)nullptr,
                                                     (const float*)nullptr, B.xh, HW1);

    // ---- encoder (conv out fp16, BN stats fp16) ----
    run_conv<96>(B.xh, B.wh2, B.c2);
    bn_stats_k<<<CH, 256>>>(B.c2, HW2, bnw2, bnb2, B.scale, B.shift);
    bnT_k<1><<<dim3(cdiv(HW2, 32), 16, BATCH), tb>>>(B.c2, B.scale, B.shift, B.d2h, HW2);

    run_conv<48>(B.d2h, B.wh3, B.c3);
    bn_stats_k<<<CH, 256>>>(B.c3, HW3, bnw3, bnb3, B.scale, B.shift);
    bnT_k<1><<<dim3(cdiv(HW3, 32), 16, BATCH), tb>>>(B.c3, B.scale, B.shift, B.d3h, HW3);

    run_conv<24>(B.d3h, B.wh4, B.c4);
    bn_stats_k<<<CH, 256>>>(B.c4, HW4, bnw4, bnb4, B.scale, B.shift);
    bnT_k<1><<<dim3(cdiv(HW4, 32), 16, BATCH), tb>>>(B.c4, B.scale, B.shift, B.d4h, HW4);

    // ---- PAM at each level ----
    run_pam(B.d2h, HW2, B.qkwh2, B.qkb2, B.vwh2, (const float*)d_in[9],
            (const float*)d_in[10], B.p2h, B);
    run_pam(B.d3h, HW3, B.qkwh3, B.qkb3, B.vwh3, (const float*)d_in[19],
            (const float*)d_in[20], B.p3h, B);
    run_pam(B.d4h, HW4, B.qkwh4, B.qkb4, B.vwh4, (const float*)d_in[29],
            (const float*)d_in[30], B.p4h, B);

    // ---- top-down upsample chain (fp16 intermediates) ----
    {
        size_t tot = (size_t)BATCH * CH * HW3;
        up_fma_k<<<(unsigned)((tot + 255) / 256), 256>>>(B.p4h, 12, 12, B.p3h, B.t3h,
                                                         24, 24, nullptr, tot);
    }
    {
        size_t tot = (size_t)BATCH * CH * HW2;
        up_fma_k<<<(unsigned)((tot + 255) / 256), 256>>>(B.t3h, 24, 24, B.p2h, B.t2h,
                                                         48, 48, nullptr, tot);
    }
    {
        size_t tot = (size_t)BATCH * CH * HW1;
        up_fma_k<<<(unsigned)((tot + 255) / 256), 256>>>(B.t2h, 48, 48, x, out,
                                                         96, 96, gamma, tot);
    }
}